// round 2
// baseline (speedup 1.0000x reference)
#include <cuda_runtime.h>
#include <cstddef>

#define BATCH 4
#define CIN   48
#define C6    288
#define C2    96
#define HH    256
#define WW    256

// 302 MB scratch for qkv = dw3x3(conv1x1(x)); q=[0,96), k=[96,192), v=[192,288)
__device__ float g_qkv[(size_t)BATCH * C6 * HH * WW];

// ---------------------------------------------------------------------------
// K1: fused 1x1 conv (48->288, bias) + depthwise 3x3 SAME (bias) -> g_qkv
// grid (16,16,B), block 352. Dynamic smem: w1 (13824) + wdw (2592) + hid (324)
// ---------------------------------------------------------------------------
__global__ void fsas_k1(const float* __restrict__ x,
                        const float* __restrict__ w1,
                        const float* __restrict__ b1,
                        const float* __restrict__ wdw,
                        const float* __restrict__ bdw) {
    extern __shared__ float sm1[];
    float* w1s  = sm1;               // C6*CIN
    float* wdws = w1s + C6 * CIN;    // C6*9
    float* hid  = wdws + C6 * 9;     // 18*18

    const int tid = threadIdx.x;
    const int b  = blockIdx.z;
    const int h0 = blockIdx.y * 16;
    const int w0 = blockIdx.x * 16;

    for (int i = tid; i < C6 * CIN; i += blockDim.x) w1s[i] = w1[i];
    for (int i = tid; i < C6 * 9;   i += blockDim.x) wdws[i] = wdw[i];

    // each thread owns one halo pixel (18x18 = 324) and register-caches x[ch]
    const int s  = tid;                 // halo index (valid if < 324)
    const int ty = s / 18, tx = s % 18;
    const int hh = h0 - 1 + ty;
    const int ww = w0 - 1 + tx;
    const bool inimg = (s < 324) && hh >= 0 && hh < HH && ww >= 0 && ww < WW;

    float xr[CIN];
    if (inimg) {
        const float* xp = x + ((size_t)b * CIN) * HH * WW + (size_t)hh * WW + ww;
        #pragma unroll
        for (int c = 0; c < CIN; c++) xr[c] = xp[(size_t)c * HH * WW];
    } else {
        #pragma unroll
        for (int c = 0; c < CIN; c++) xr[c] = 0.0f;
    }

    // interior pixel for depthwise output (threads 0..255)
    const int py = tid >> 4, px = tid & 15;

    __syncthreads();

    for (int o = 0; o < C6; o++) {
        if (s < 324) {
            // hidden = conv1x1 at halo pixel; outside image -> 0 (SAME zero-pad of hidden)
            float a0 = 0.f, a1 = 0.f, a2 = 0.f, a3 = 0.f;
            const float* wrow = &w1s[o * CIN];
            #pragma unroll
            for (int c = 0; c < CIN; c += 4) {
                a0 += wrow[c + 0] * xr[c + 0];
                a1 += wrow[c + 1] * xr[c + 1];
                a2 += wrow[c + 2] * xr[c + 2];
                a3 += wrow[c + 3] * xr[c + 3];
            }
            hid[s] = inimg ? ((a0 + a1) + (a2 + a3) + b1[o]) : 0.0f;
        }
        __syncthreads();
        if (tid < 256) {
            const float* wd = &wdws[o * 9];
            float acc = bdw[o];
            #pragma unroll
            for (int dy = 0; dy < 3; dy++)
                #pragma unroll
                for (int dx = 0; dx < 3; dx++)
                    acc += wd[dy * 3 + dx] * hid[(py + dy) * 18 + (px + dx)];
            g_qkv[(((size_t)b * C6 + o) * HH + (h0 + py)) * WW + (w0 + px)] = acc;
        }
        __syncthreads();
    }
}

// ---------------------------------------------------------------------------
// K2: per 64-col segment of one row: circular conv (8x8 on flat 64 chunk),
// channel LayerNorm (96), v*normed, 1x1 conv 96->48, write output.
// grid (4, 256, B), block 256.
// Dynamic smem: qs/ks/vs/os (4*6144) + wout (4608) + mu/rs (128)
// ---------------------------------------------------------------------------
__global__ void fsas_k2(const float* __restrict__ gamma,
                        const float* __restrict__ beta,
                        const float* __restrict__ wout,
                        const float* __restrict__ bout,
                        float* __restrict__ out) {
    extern __shared__ float sm2[];
    float* qs   = sm2;                 // C2*64
    float* ks   = qs + C2 * 64;
    float* vs   = ks + C2 * 64;
    float* os_  = vs + C2 * 64;
    float* wos  = os_ + C2 * 64;       // CIN*C2
    float* mus  = wos + CIN * C2;      // 64
    float* rss  = mus + 64;            // 64

    const int tid = threadIdx.x;
    const int b  = blockIdx.z;
    const int h  = blockIdx.y;
    const int w0 = blockIdx.x * 64;

    const size_t plane = (size_t)HH * WW;

    for (int i = tid; i < C2 * 64; i += 256) {
        const int ch = i >> 6, z = i & 63;
        const size_t off = (((size_t)b * C6 + ch) * HH + h) * WW + w0 + z;
        qs[i] = g_qkv[off];
        ks[i] = g_qkv[off + (size_t)C2 * plane];
        vs[i] = g_qkv[off + (size_t)(2 * C2) * plane];
    }
    for (int i = tid; i < CIN * C2; i += 256) wos[i] = wout[i];
    __syncthreads();

    // 2D circular convolution within each 64-float chunk viewed as 8x8
    for (int i = tid; i < C2 * 64; i += 256) {
        const int ch = i >> 6, z = i & 63;
        const int m = z >> 3, n = z & 7;
        const float* q = &qs[ch * 64];
        const float* k = &ks[ch * 64];
        float acc = 0.0f;
        #pragma unroll
        for (int p = 0; p < 8; p++) {
            const int mm = ((m - p) & 7) * 8;
            #pragma unroll
            for (int r = 0; r < 8; r++)
                acc += q[p * 8 + r] * k[mm + ((n - r) & 7)];
        }
        os_[i] = acc;
    }
    __syncthreads();

    // LayerNorm stats over 96 channels per pixel (population variance)
    if (tid < 64) {
        float sum = 0.f, sq = 0.f;
        #pragma unroll
        for (int ch = 0; ch < C2; ch++) {
            const float v = os_[ch * 64 + tid];
            sum += v; sq += v * v;
        }
        const float mu  = sum * (1.0f / C2);
        const float var = sq * (1.0f / C2) - mu * mu;
        mus[tid] = mu;
        rss[tid] = rsqrtf(var + 1e-5f);
    }
    __syncthreads();

    // nv = v * (gamma*(o-mu)*rstd + beta), reuse qs
    for (int i = tid; i < C2 * 64; i += 256) {
        const int ch = i >> 6, z = i & 63;
        const float nrm = (os_[i] - mus[z]) * rss[z] * gamma[ch] + beta[ch];
        qs[i] = vs[i] * nrm;
    }
    __syncthreads();

    // final 1x1 conv 96->48
    for (int i = tid; i < CIN * 64; i += 256) {
        const int co = i >> 6, z = i & 63;
        const float* wr = &wos[co * C2];
        float a0 = 0.f, a1 = 0.f, a2 = 0.f, a3 = 0.f;
        #pragma unroll
        for (int ch = 0; ch < C2; ch += 4) {
            a0 += wr[ch + 0] * qs[(ch + 0) * 64 + z];
            a1 += wr[ch + 1] * qs[(ch + 1) * 64 + z];
            a2 += wr[ch + 2] * qs[(ch + 2) * 64 + z];
            a3 += wr[ch + 3] * qs[(ch + 3) * 64 + z];
        }
        out[(((size_t)b * CIN + co) * HH + h) * WW + w0 + z] =
            (a0 + a1) + (a2 + a3) + bout[co];
    }
}

// ---------------------------------------------------------------------------
extern "C" void kernel_launch(void* const* d_in, const int* in_sizes, int n_in,
                              void* d_out, int out_size) {
    const float* x        = (const float*)d_in[0];
    const float* w_hidden = (const float*)d_in[1];
    const float* b_hidden = (const float*)d_in[2];
    const float* w_dw     = (const float*)d_in[3];
    const float* b_dw     = (const float*)d_in[4];
    const float* gamma    = (const float*)d_in[5];
    const float* beta     = (const float*)d_in[6];
    const float* w_out    = (const float*)d_in[7];
    const float* b_out    = (const float*)d_in[8];
    float* out = (float*)d_out;

    const int smem1 = (C6 * CIN + C6 * 9 + 324) * sizeof(float);          // ~67 KB
    const int smem2 = (4 * C2 * 64 + CIN * C2 + 128) * sizeof(float);     // ~117 KB
    cudaFuncSetAttribute(fsas_k1, cudaFuncAttributeMaxDynamicSharedMemorySize, smem1);
    cudaFuncSetAttribute(fsas_k2, cudaFuncAttributeMaxDynamicSharedMemorySize, smem2);

    fsas_k1<<<dim3(16, 16, BATCH), 352, smem1>>>(x, w_hidden, b_hidden, w_dw, b_dw);
    fsas_k2<<<dim3(4, 256, BATCH), 256, smem2>>>(gamma, beta, w_out, b_out, out);
}

// round 3
// speedup vs baseline: 1.4402x; 1.4402x over previous
#include <cuda_runtime.h>
#include <cstddef>

#define BATCH 4
#define CIN   48
#define C6    288
#define C2    96
#define HH    256
#define WW    256

// 302 MB scratch for qkv = dw3x3(conv1x1(x)); q=[0,96), k=[96,192), v=[192,288)
__device__ float g_qkv[(size_t)BATCH * C6 * HH * WW];

// ---------------------------------------------------------------------------
// K1: fused 1x1 conv (48->288, bias) + depthwise 3x3 SAME (bias) -> g_qkv
// grid (16,16,B), block 352. Channels processed in pairs (half the syncs).
// ---------------------------------------------------------------------------
__global__ void __launch_bounds__(352, 2)
fsas_k1(const float* __restrict__ x,
        const float* __restrict__ w1,
        const float* __restrict__ b1,
        const float* __restrict__ wdw,
        const float* __restrict__ bdw) {
    extern __shared__ float sm1[];
    float* w1s  = sm1;               // C6*CIN
    float* wdws = w1s + C6 * CIN;    // C6*9
    float* hid0 = wdws + C6 * 9;     // 324
    float* hid1 = hid0 + 324;        // 324

    const int tid = threadIdx.x;
    const int b  = blockIdx.z;
    const int h0 = blockIdx.y * 16;
    const int w0 = blockIdx.x * 16;

    for (int i = tid; i < C6 * CIN; i += blockDim.x) w1s[i] = w1[i];
    for (int i = tid; i < C6 * 9;   i += blockDim.x) wdws[i] = wdw[i];

    // each thread owns one halo pixel (18x18 = 324) and register-caches x[ch]
    const int s  = tid;
    const int ty = s / 18, tx = s % 18;
    const int hh = h0 - 1 + ty;
    const int ww = w0 - 1 + tx;
    const bool inimg = (s < 324) && hh >= 0 && hh < HH && ww >= 0 && ww < WW;

    float xr[CIN];
    if (inimg) {
        const float* xp = x + ((size_t)b * CIN) * HH * WW + (size_t)hh * WW + ww;
        #pragma unroll
        for (int c = 0; c < CIN; c++) xr[c] = xp[(size_t)c * HH * WW];
    } else {
        #pragma unroll
        for (int c = 0; c < CIN; c++) xr[c] = 0.0f;
    }

    const int py = tid >> 4, px = tid & 15;

    __syncthreads();

    for (int o = 0; o < C6; o += 2) {
        if (s < 324) {
            float a0 = 0.f, a1 = 0.f, a2 = 0.f, a3 = 0.f;
            float c0 = 0.f, c1 = 0.f, c2 = 0.f, c3 = 0.f;
            const float* wr0 = &w1s[o * CIN];
            const float* wr1 = &w1s[(o + 1) * CIN];
            #pragma unroll
            for (int c = 0; c < CIN; c += 4) {
                a0 += wr0[c + 0] * xr[c + 0];
                a1 += wr0[c + 1] * xr[c + 1];
                a2 += wr0[c + 2] * xr[c + 2];
                a3 += wr0[c + 3] * xr[c + 3];
                c0 += wr1[c + 0] * xr[c + 0];
                c1 += wr1[c + 1] * xr[c + 1];
                c2 += wr1[c + 2] * xr[c + 2];
                c3 += wr1[c + 3] * xr[c + 3];
            }
            hid0[s] = inimg ? ((a0 + a1) + (a2 + a3) + b1[o])     : 0.0f;
            hid1[s] = inimg ? ((c0 + c1) + (c2 + c3) + b1[o + 1]) : 0.0f;
        }
        __syncthreads();
        if (tid < 256) {
            const float* wd0 = &wdws[o * 9];
            const float* wd1 = wd0 + 9;
            float acc0 = bdw[o];
            float acc1 = bdw[o + 1];
            #pragma unroll
            for (int dy = 0; dy < 3; dy++)
                #pragma unroll
                for (int dx = 0; dx < 3; dx++) {
                    const int hs = (py + dy) * 18 + (px + dx);
                    acc0 += wd0[dy * 3 + dx] * hid0[hs];
                    acc1 += wd1[dy * 3 + dx] * hid1[hs];
                }
            const size_t base = (((size_t)b * C6 + o) * HH + (h0 + py)) * WW + (w0 + px);
            g_qkv[base] = acc0;
            g_qkv[base + (size_t)HH * WW] = acc1;
        }
        __syncthreads();
    }
}

// ---------------------------------------------------------------------------
// K2: per 64-col segment of one row: circular conv (8x8 on flat 64 chunk),
// channel LayerNorm (96), v*normed, 1x1 conv 96->48, write output.
// grid (4, 256, B), block 256, 2 CTAs/SM.
// ---------------------------------------------------------------------------
#define NVP 100   // padded stride for transposed nv buffer

__global__ void __launch_bounds__(256, 2)
fsas_k2(const float* __restrict__ gamma,
        const float* __restrict__ beta,
        const float* __restrict__ wout,
        const float* __restrict__ bout,
        float* __restrict__ out) {
    extern __shared__ float sm2[];
    float* qs   = sm2;                 // max(C2*64, 64*NVP) = 6400 (reused for nv)
    float* ks   = qs + 64 * NVP;       // C2*64 (reused for circ-conv output)
    float* vs   = ks + C2 * 64;        // C2*64
    float* wos  = vs + C2 * 64;        // CIN*C2
    float* mus  = wos + CIN * C2;      // 64
    float* rss  = mus + 64;            // 64
    float* gms  = rss + 64;            // C2
    float* bts  = gms + C2;            // C2

    const int tid = threadIdx.x;
    const int b  = blockIdx.z;
    const int h  = blockIdx.y;
    const int w0 = blockIdx.x * 64;

    const size_t plane = (size_t)HH * WW;
    const size_t base  = (((size_t)b * C6) * HH + h) * WW + w0;

    // ---- load q,k,v tiles (float4) + weights -----------------------------
    for (int i4 = tid; i4 < C2 * 16; i4 += 256) {
        const int ch = i4 >> 4, z4 = (i4 & 15) << 2;
        const size_t off = base + (size_t)ch * plane + z4;
        *(float4*)&qs[ch * 64 + z4] = *(const float4*)&g_qkv[off];
        *(float4*)&ks[ch * 64 + z4] = *(const float4*)&g_qkv[off + (size_t)C2 * plane];
        *(float4*)&vs[ch * 64 + z4] = *(const float4*)&g_qkv[off + (size_t)(2 * C2) * plane];
    }
    for (int i = tid; i < CIN * C2; i += 256) wos[i] = wout[i];
    if (tid < C2) { gms[tid] = gamma[tid]; bts[tid] = beta[tid]; }
    __syncthreads();

    // ---- 2D circular conv: thread owns 3 (ch,m)-rows, all-register inner --
    float og[3][8];
    #pragma unroll
    for (int i = 0; i < 3; i++) {
        const int j  = tid + 256 * i;        // 0..767
        const int ch = j >> 3, m = j & 7;
        const float* qb = &qs[ch * 64];
        const float* kb = &ks[ch * 64];
        float o0=0.f,o1=0.f,o2=0.f,o3=0.f,o4=0.f,o5=0.f,o6=0.f,o7=0.f;
        #pragma unroll
        for (int p = 0; p < 8; p++) {
            float4 qa = *(const float4*)&qb[p * 8];
            float4 qc = *(const float4*)&qb[p * 8 + 4];
            const int kr = ((m - p) & 7) * 8;
            float4 ka = *(const float4*)&kb[kr];
            float4 kc = *(const float4*)&kb[kr + 4];
            const float qv[8] = {qa.x,qa.y,qa.z,qa.w,qc.x,qc.y,qc.z,qc.w};
            const float kv[8] = {ka.x,ka.y,ka.z,ka.w,kc.x,kc.y,kc.z,kc.w};
            #pragma unroll
            for (int r = 0; r < 8; r++) {
                o0 += qv[r] * kv[(0 - r) & 7];
                o1 += qv[r] * kv[(1 - r) & 7];
                o2 += qv[r] * kv[(2 - r) & 7];
                o3 += qv[r] * kv[(3 - r) & 7];
                o4 += qv[r] * kv[(4 - r) & 7];
                o5 += qv[r] * kv[(5 - r) & 7];
                o6 += qv[r] * kv[(6 - r) & 7];
                o7 += qv[r] * kv[(7 - r) & 7];
            }
        }
        og[i][0]=o0; og[i][1]=o1; og[i][2]=o2; og[i][3]=o3;
        og[i][4]=o4; og[i][5]=o5; og[i][6]=o6; og[i][7]=o7;
    }
    __syncthreads();           // everyone done reading k
    #pragma unroll
    for (int i = 0; i < 3; i++) {
        const int j = tid + 256 * i;
        *(float4*)&ks[j * 8]     = *(float4*)&og[i][0];   // os overwrites ks
        *(float4*)&ks[j * 8 + 4] = *(float4*)&og[i][4];
    }
    __syncthreads();

    // ---- LayerNorm stats over 96 channels per pixel ----------------------
    if (tid < 64) {
        float sum = 0.f, sq = 0.f;
        #pragma unroll
        for (int ch = 0; ch < C2; ch++) {
            const float v = ks[ch * 64 + tid];
            sum += v; sq += v * v;
        }
        const float mu  = sum * (1.0f / C2);
        const float var = sq * (1.0f / C2) - mu * mu;
        mus[tid] = mu;
        rss[tid] = rsqrtf(var + 1e-5f);
    }
    __syncthreads();

    // ---- nv = v * normed, stored transposed [z][ch] (pad 100) into qs ----
    for (int i = tid; i < C2 * 64; i += 256) {
        const int ch = i >> 6, z = i & 63;
        const float nrm = (ks[i] - mus[z]) * rss[z] * gms[ch] + bts[ch];
        qs[z * NVP + ch] = vs[i] * nrm;
    }
    __syncthreads();

    // ---- final 1x1 conv 96->48: thread = (q4, z), 12 co each -------------
    {
        const int q4 = tid >> 6;           // 0..3
        const int z  = tid & 63;
        float acc[12];
        #pragma unroll
        for (int c = 0; c < 12; c++) acc[c] = 0.f;
        const float* nvz = &qs[z * NVP];
        #pragma unroll
        for (int ch = 0; ch < C2; ch += 4) {
            const float4 nv4 = *(const float4*)&nvz[ch];
            #pragma unroll
            for (int c = 0; c < 12; c++) {
                const float4 w4 = *(const float4*)&wos[(q4 * 12 + c) * C2 + ch];
                acc[c] += w4.x * nv4.x + w4.y * nv4.y + w4.z * nv4.z + w4.w * nv4.w;
            }
        }
        const size_t obase = (((size_t)b * CIN + q4 * 12) * HH + h) * WW + w0 + z;
        #pragma unroll
        for (int c = 0; c < 12; c++)
            out[obase + (size_t)c * HH * WW] = acc[c] + bout[q4 * 12 + c];
    }
}

// ---------------------------------------------------------------------------
extern "C" void kernel_launch(void* const* d_in, const int* in_sizes, int n_in,
                              void* d_out, int out_size) {
    const float* x        = (const float*)d_in[0];
    const float* w_hidden = (const float*)d_in[1];
    const float* b_hidden = (const float*)d_in[2];
    const float* w_dw     = (const float*)d_in[3];
    const float* b_dw     = (const float*)d_in[4];
    const float* gamma    = (const float*)d_in[5];
    const float* beta     = (const float*)d_in[6];
    const float* w_out    = (const float*)d_in[7];
    const float* b_out    = (const float*)d_in[8];
    float* out = (float*)d_out;

    const int smem1 = (C6 * CIN + C6 * 9 + 2 * 324) * sizeof(float);
    const int smem2 = (64 * NVP + 2 * C2 * 64 + CIN * C2 + 128 + 2 * C2) * sizeof(float);
    cudaFuncSetAttribute(fsas_k1, cudaFuncAttributeMaxDynamicSharedMemorySize, smem1);
    cudaFuncSetAttribute(fsas_k2, cudaFuncAttributeMaxDynamicSharedMemorySize, smem2);

    fsas_k1<<<dim3(16, 16, BATCH), 352, smem1>>>(x, w_hidden, b_hidden, w_dw, b_dw);
    fsas_k2<<<dim3(4, 256, BATCH), 256, smem2>>>(gamma, beta, w_out, b_out, out);
}